// round 10
// baseline (speedup 1.0000x reference)
#include <cuda_runtime.h>

#define T_STEPS 512
#define BATCH   64
#define HID     512
#define GATES3  1536
#define NB_REC  128
#define NT_REC  256
#define WR      516   // float stride for smem rows (padded: conflict-free)
#define CLU     16    // cluster size (one col-group set)

// ---------------- scratch (static device allocations; no cudaMalloc) ----------------
__device__ float g_xg[(size_t)T_STEPS * BATCH * GATES3]; // precomputed input gates
__device__ float g_y0[(size_t)T_STEPS * BATCH * HID];    // layer-0 output
__device__ float g_hx[2 * BATCH * HID];                  // h exchange (fallback path only)
__device__ unsigned g_flags[NB_REC];                     // fallback per-block step flags
__device__ unsigned g_end_cnt[8];
__device__ volatile unsigned g_end_gen[8];

// ---------------- packed fp32x2 FMA (Blackwell FFMA2) ----------------
__device__ __forceinline__ float2 ffma2(float2 a, float2 b, float2 c) {
    float2 d;
    asm("fma.rn.f32x2 %0, %1, %2, %3;"
        : "=l"(reinterpret_cast<unsigned long long&>(d))
        : "l"(reinterpret_cast<unsigned long long&>(a)),
          "l"(reinterpret_cast<unsigned long long&>(b)),
          "l"(reinterpret_cast<unsigned long long&>(c)));
    return d;
}

__device__ __forceinline__ float fast_sigmoid(float x) {
    return __fdividef(1.f, 1.f + __expf(-x));
}
__device__ __forceinline__ float fast_tanh(float x) {
    float r;
    asm("tanh.approx.f32 %0, %1;" : "=f"(r) : "f"(x));
    return r;
}

__device__ __forceinline__ unsigned smem_u32(const void* p) {
    unsigned a;
    asm("{ .reg .u64 t; cvta.to.shared.u64 t, %1; cvt.u32.u64 %0, t; }"
        : "=r"(a) : "l"(p));
    return a;
}

// ---------------- GEMM: out[M,N] = A[M,K] * W[N,K]^T + bias (R2 version, known-good) ----
__global__ void __launch_bounds__(256) gemm_bias_kernel(
    const float* __restrict__ A, const float* __restrict__ W,
    const float* __restrict__ bias, float* __restrict__ out, int K)
{
    __shared__ float As[16 * 132];
    __shared__ float Bs[16 * 132];

    const int tid = threadIdx.x;
    const int m0 = blockIdx.y * 128;
    const int n0 = blockIdx.x * 128;
    const int tm = tid >> 4;
    const int tn = tid & 15;

    float2 c2[8][4];
#pragma unroll
    for (int i = 0; i < 8; ++i)
#pragma unroll
        for (int p = 0; p < 4; ++p) c2[i][p] = make_float2(0.f, 0.f);

    for (int kt = 0; kt < K; kt += 16) {
#pragma unroll
        for (int u = 0; u < 2; ++u) {
            int s   = tid + u * 256;
            int row = s >> 2;
            int c4  = s & 3;
            float4 av = *(const float4*)(A + (size_t)(m0 + row) * K + kt + c4 * 4);
            As[(c4 * 4 + 0) * 132 + row] = av.x;
            As[(c4 * 4 + 1) * 132 + row] = av.y;
            As[(c4 * 4 + 2) * 132 + row] = av.z;
            As[(c4 * 4 + 3) * 132 + row] = av.w;
            float4 bv = *(const float4*)(W + (size_t)(n0 + row) * K + kt + c4 * 4);
            Bs[(c4 * 4 + 0) * 132 + row] = bv.x;
            Bs[(c4 * 4 + 1) * 132 + row] = bv.y;
            Bs[(c4 * 4 + 2) * 132 + row] = bv.z;
            Bs[(c4 * 4 + 3) * 132 + row] = bv.w;
        }
        __syncthreads();

#pragma unroll
        for (int kb = 0; kb < 16; ++kb) {
            float4 a0 = *(const float4*)(As + kb * 132 + tm * 8);
            float4 a1 = *(const float4*)(As + kb * 132 + tm * 8 + 4);
            float4 b0 = *(const float4*)(Bs + kb * 132 + tn * 8);
            float4 b1 = *(const float4*)(Bs + kb * 132 + tn * 8 + 4);
            float av[8] = {a0.x, a0.y, a0.z, a0.w, a1.x, a1.y, a1.z, a1.w};
            float2 bp[4] = {make_float2(b0.x, b0.y), make_float2(b0.z, b0.w),
                            make_float2(b1.x, b1.y), make_float2(b1.z, b1.w)};
#pragma unroll
            for (int i = 0; i < 8; ++i) {
                float2 as = make_float2(av[i], av[i]);
#pragma unroll
                for (int p = 0; p < 4; ++p) c2[i][p] = ffma2(as, bp[p], c2[i][p]);
            }
        }
        __syncthreads();
    }

    const float4 bb0 = *(const float4*)(bias + n0 + tn * 8);
    const float4 bb1 = *(const float4*)(bias + n0 + tn * 8 + 4);
#pragma unroll
    for (int i = 0; i < 8; ++i) {
        int m = m0 + tm * 8 + i;
        float4 o0 = make_float4(c2[i][0].x + bb0.x, c2[i][0].y + bb0.y,
                                c2[i][1].x + bb0.z, c2[i][1].y + bb0.w);
        float4 o1 = make_float4(c2[i][2].x + bb1.x, c2[i][2].y + bb1.y,
                                c2[i][3].x + bb1.z, c2[i][3].y + bb1.w);
        float* dst = out + (size_t)m * GATES3 + n0 + tn * 8;
        *(float4*)(dst)     = o0;
        *(float4*)(dst + 4) = o1;
    }
}

// =====================================================================================
// CLUSTER recurrence: 16-CTA cluster = one batch-group's 16 col-blocks.
// h exchanged via DSMEM (st.shared::cluster) into double-buffered smem + mbarrier.
// smem layout (floats): [0..4) mbar, [4..4+96*WR) W, then 2 x (8*WR) h buffers.
// =====================================================================================
__global__ void __launch_bounds__(NT_REC, 1) gru_rec_cluster(
    const float* __restrict__ xg, const float* __restrict__ Whh,
    const float* __restrict__ bhh, float* __restrict__ y,
    float* __restrict__ hn_out)
{
    extern __shared__ float smem[];
    float* Ws  = smem + 4;                    // 96 rows x 516
    float* hs0 = Ws + 96 * WR;                // buffer 0: 8 x 516
    float* hs1 = hs0 + 8 * WR;                // buffer 1: 8 x 516

    const int tid  = threadIdx.x;
    const int bid  = blockIdx.x;
    const int cg   = bid & 15;                // == cluster rank
    const int grp  = bid >> 4;
    const int j0   = cg * 32;
    const int b0   = grp * 8;
    const int col  = tid >> 3;                // 0..31
    const int bsub = tid & 7;                 // 0..7
    const int b    = b0 + bsub;
    const int j    = j0 + col;

    const unsigned mbar   = smem_u32(smem);
    const unsigned hs0u   = smem_u32(hs0);
    const unsigned hOffB  = (unsigned)((bsub * WR + j) * 4);   // byte offset inside an h buffer
    const unsigned bufStride = (unsigned)(8 * WR * 4);

    // init mbarrier (16 arrivals = one per producer CTA)
    if (tid == 0) {
        asm volatile("mbarrier.init.shared.b64 [%0], %1;" :: "r"(mbar), "r"(CLU) : "memory");
    }

    // one-time: W_hh slice
    for (int idx = tid; idx < 96 * 512; idx += NT_REC) {
        int row = idx >> 9;
        int k   = idx & 511;
        int g   = row >> 5;
        int c   = row & 31;
        Ws[row * WR + k] = Whh[(size_t)(g * HID + j0 + c) * HID + k];
    }
    for (int idx = tid; idx < 16 * WR; idx += NT_REC) hs0[idx] = 0.f;

    const float bhr = bhh[j];
    const float bhz = bhh[HID + j];
    const float bhn = bhh[2 * HID + j];

    const float* wr = Ws + col * WR;
    const float* wz = Ws + (32 + col) * WR;
    const float* wn = Ws + (64 + col) * WR;

    const size_t xofs = (size_t)b * GATES3 + j;
    float xr = xg[xofs];
    float xz = xg[xofs + HID];
    float xn = xg[xofs + 2 * HID];

    float hp = 0.f;
    __syncthreads();
    // cluster-wide: mbarrier init + zeroed buffers visible before any remote store
    asm volatile("barrier.cluster.arrive.aligned;" ::: "memory");
    asm volatile("barrier.cluster.wait.aligned;" ::: "memory");

    for (int t = 0; t < T_STEPS; ++t) {
        if (t > 0) {
            // wait for all 16 producers' arrivals (data already in our smem)
            const unsigned parity = (unsigned)((t + 1) & 1);
            unsigned done;
            asm volatile(
                "{\n\t"
                ".reg .pred p;\n\t"
                "mbarrier.try_wait.parity.acquire.cluster.shared::cta.b64 p, [%1], %2;\n\t"
                "selp.b32 %0, 1, 0, p;\n\t"
                "}"
                : "=r"(done) : "r"(mbar), "r"(parity) : "memory");
            if (!done) {
                asm volatile(
                    "{\n\t"
                    ".reg .pred P1;\n\t"
                    "WL_%=:\n\t"
                    "mbarrier.try_wait.parity.acquire.cluster.shared::cta.b64 P1, [%0], %1, 0x989680;\n\t"
                    "@P1 bra.uni WD_%=;\n\t"
                    "bra.uni WL_%=;\n\t"
                    "WD_%=:\n\t"
                    "}"
                    :: "r"(mbar), "r"(parity) : "memory");
            }
        }

        // prefetch next step's xg
        float nxr = 0.f, nxz = 0.f, nxn = 0.f;
        if (t + 1 < T_STEPS) {
            const float* xp = xg + (size_t)(t + 1) * BATCH * GATES3 + xofs;
            nxr = __ldg(xp);
            nxz = __ldg(xp + HID);
            nxn = __ldg(xp + 2 * HID);
        }

        // full-k dot from buffer t&1
        const float* hb = (t & 1) ? (hs1 + bsub * WR) : (hs0 + bsub * WR);
        float2 r0 = {0, 0}, r1 = {0, 0};
        float2 z0 = {0, 0}, z1 = {0, 0};
        float2 n0 = {0, 0}, n1 = {0, 0};
#pragma unroll 8
        for (int k = 0; k < HID; k += 8) {
            float4 h0 = *(const float4*)(hb + k);
            float4 h1 = *(const float4*)(hb + k + 4);
            float4 a0 = *(const float4*)(wr + k);
            float4 a1 = *(const float4*)(wr + k + 4);
            float4 c0 = *(const float4*)(wz + k);
            float4 c1 = *(const float4*)(wz + k + 4);
            float4 d0 = *(const float4*)(wn + k);
            float4 d1 = *(const float4*)(wn + k + 4);
            r0 = ffma2(make_float2(a0.x, a0.y), make_float2(h0.x, h0.y), r0);
            r1 = ffma2(make_float2(a0.z, a0.w), make_float2(h0.z, h0.w), r1);
            z0 = ffma2(make_float2(c0.x, c0.y), make_float2(h0.x, h0.y), z0);
            z1 = ffma2(make_float2(c0.z, c0.w), make_float2(h0.z, h0.w), z1);
            n0 = ffma2(make_float2(d0.x, d0.y), make_float2(h0.x, h0.y), n0);
            n1 = ffma2(make_float2(d0.z, d0.w), make_float2(h0.z, h0.w), n1);
            r0 = ffma2(make_float2(a1.x, a1.y), make_float2(h1.x, h1.y), r0);
            r1 = ffma2(make_float2(a1.z, a1.w), make_float2(h1.z, h1.w), r1);
            z0 = ffma2(make_float2(c1.x, c1.y), make_float2(h1.x, h1.y), z0);
            z1 = ffma2(make_float2(c1.z, c1.w), make_float2(h1.z, h1.w), z1);
            n0 = ffma2(make_float2(d1.x, d1.y), make_float2(h1.x, h1.y), n0);
            n1 = ffma2(make_float2(d1.z, d1.w), make_float2(h1.z, h1.w), n1);
        }
        float hr = r0.x + r0.y + r1.x + r1.y + bhr;
        float hz = z0.x + z0.y + z1.x + z1.y + bhz;
        float hn = n0.x + n0.y + n1.x + n1.y + bhn;

        float rg = fast_sigmoid(xr + hr);
        float zg = fast_sigmoid(xz + hz);
        float ng = fast_tanh(xn + rg * hn);
        hp = (1.f - zg) * ng + zg * hp;

        if (t + 1 < T_STEPS) {
            // broadcast own h to ALL 16 CTAs' buffer (t+1)&1 via DSMEM
            const unsigned dstOff = hs0u + ((unsigned)((t + 1) & 1)) * bufStride + hOffB;
#pragma unroll
            for (int r = 0; r < CLU; ++r) {
                unsigned ra;
                asm volatile("mapa.shared::cluster.u32 %0, %1, %2;"
                             : "=r"(ra) : "r"(dstOff), "r"(r));
                asm volatile("st.shared::cluster.f32 [%0], %1;"
                             :: "r"(ra), "f"(hp) : "memory");
            }
            __syncthreads();
            // one release-arrive per peer (16 threads cover the cluster)
            if (tid < CLU) {
                asm volatile("fence.acq_rel.cluster;" ::: "memory");
                unsigned rb;
                asm volatile("mapa.shared::cluster.u32 %0, %1, %2;"
                             : "=r"(rb) : "r"(mbar), "r"(tid));
                asm volatile("mbarrier.arrive.release.cluster.shared::cluster.b64 _, [%0];"
                             :: "r"(rb) : "memory");
            }
        }

        // off critical path: outputs
        y[((size_t)t * BATCH + b) * HID + j] = hp;
        if (t == T_STEPS - 1) hn_out[(size_t)b * HID + j] = hp;

        xr = nxr; xz = nxz; xn = nxn;
    }

    asm volatile("barrier.cluster.arrive.aligned;" ::: "memory");
    asm volatile("barrier.cluster.wait.aligned;" ::: "memory");
}

// =====================================================================================
// FALLBACK recurrence (R9 flag-based; used if 16-CTA clusters unavailable)
// =====================================================================================
__global__ void __launch_bounds__(NT_REC, 1) gru_rec_fallback(
    const float* __restrict__ xg, const float* __restrict__ Whh,
    const float* __restrict__ bhh, float* __restrict__ y,
    float* __restrict__ hn_out)
{
    extern __shared__ float smem[];
    float* Ws = smem;
    float* hs = smem + 96 * WR;

    const int tid  = threadIdx.x;
    const int bid  = blockIdx.x;
    const int cg   = bid & 15;
    const int grp  = bid >> 4;
    const int j0   = cg * 32;
    const int b0   = grp * 8;
    const int col  = tid >> 3;
    const int bsub = tid & 7;
    const int b    = b0 + bsub;
    const int j    = j0 + col;

    for (int idx = tid; idx < 96 * 512; idx += NT_REC) {
        int row = idx >> 9;
        int k   = idx & 511;
        int g   = row >> 5;
        int c   = row & 31;
        Ws[row * WR + k] = Whh[(size_t)(g * HID + j0 + c) * HID + k];
    }
    for (int idx = tid; idx < 8 * WR; idx += NT_REC) hs[idx] = 0.f;

    const float bhr = bhh[j];
    const float bhz = bhh[HID + j];
    const float bhn = bhh[2 * HID + j];

    const float* wr = Ws + col * WR;
    const float* wz = Ws + (32 + col) * WR;
    const float* wn = Ws + (64 + col) * WR;
    const float* hb = hs + bsub * WR;

    const size_t xofs = (size_t)b * GATES3 + j;
    float xr = xg[xofs];
    float xz = xg[xofs + HID];
    float xn = xg[xofs + 2 * HID];

    const int skq = tid >> 1;
    const int sk4 = skq * 4;
    const int scb = skq >> 3;
    const int sbh = tid & 1;
    const bool stage_mine = (scb != cg);

    float hp = 0.f;
    __syncthreads();

    for (int t = 0; t < T_STEPS; ++t) {
        if (t > 0) {
            if (tid < 16 && tid != cg) {
                const unsigned* fp = &g_flags[grp * 16 + tid];
                unsigned v;
                do {
                    asm volatile("ld.acquire.gpu.global.u32 %0, [%1];" : "=r"(v) : "l"(fp));
                } while (v < (unsigned)t);
            }
            __syncthreads();
            if (stage_mine) {
                const float* hsrc = g_hx + (size_t)(t & 1) * BATCH * HID;
#pragma unroll
                for (int i = 0; i < 4; ++i) {
                    int bb = sbh * 4 + i;
                    float4 hv = __ldcg((const float4*)(hsrc + (size_t)(b0 + bb) * HID + sk4));
                    *(float4*)(hs + bb * WR + sk4) = hv;
                }
            }
            __syncthreads();
        }

        float nxr = 0.f, nxz = 0.f, nxn = 0.f;
        if (t + 1 < T_STEPS) {
            const float* xp = xg + (size_t)(t + 1) * BATCH * GATES3 + xofs;
            nxr = __ldg(xp);
            nxz = __ldg(xp + HID);
            nxn = __ldg(xp + 2 * HID);
        }

        float2 r0 = {0, 0}, r1 = {0, 0};
        float2 z0 = {0, 0}, z1 = {0, 0};
        float2 n0 = {0, 0}, n1 = {0, 0};
#pragma unroll 8
        for (int k = 0; k < HID; k += 8) {
            float4 h0 = *(const float4*)(hb + k);
            float4 h1 = *(const float4*)(hb + k + 4);
            float4 a0 = *(const float4*)(wr + k);
            float4 a1 = *(const float4*)(wr + k + 4);
            float4 c0 = *(const float4*)(wz + k);
            float4 c1 = *(const float4*)(wz + k + 4);
            float4 d0 = *(const float4*)(wn + k);
            float4 d1 = *(const float4*)(wn + k + 4);
            r0 = ffma2(make_float2(a0.x, a0.y), make_float2(h0.x, h0.y), r0);
            r1 = ffma2(make_float2(a0.z, a0.w), make_float2(h0.z, h0.w), r1);
            z0 = ffma2(make_float2(c0.x, c0.y), make_float2(h0.x, h0.y), z0);
            z1 = ffma2(make_float2(c0.z, c0.w), make_float2(h0.z, h0.w), z1);
            n0 = ffma2(make_float2(d0.x, d0.y), make_float2(h0.x, h0.y), n0);
            n1 = ffma2(make_float2(d0.z, d0.w), make_float2(h0.z, h0.w), n1);
            r0 = ffma2(make_float2(a1.x, a1.y), make_float2(h1.x, h1.y), r0);
            r1 = ffma2(make_float2(a1.z, a1.w), make_float2(h1.z, h1.w), r1);
            z0 = ffma2(make_float2(c1.x, c1.y), make_float2(h1.x, h1.y), z0);
            z1 = ffma2(make_float2(c1.z, c1.w), make_float2(h1.z, h1.w), z1);
            n0 = ffma2(make_float2(d1.x, d1.y), make_float2(h1.x, h1.y), n0);
            n1 = ffma2(make_float2(d1.z, d1.w), make_float2(h1.z, h1.w), n1);
        }
        float hr = r0.x + r0.y + r1.x + r1.y + bhr;
        float hz = z0.x + z0.y + z1.x + z1.y + bhz;
        float hn = n0.x + n0.y + n1.x + n1.y + bhn;

        float rg = fast_sigmoid(xr + hr);
        float zg = fast_sigmoid(xz + hz);
        float ng = fast_tanh(xn + rg * hn);
        hp = (1.f - zg) * ng + zg * hp;

        {
            float* hdst = g_hx + (size_t)((t + 1) & 1) * BATCH * HID + (size_t)b * HID + j;
            asm volatile("st.global.cg.f32 [%0], %1;" :: "l"(hdst), "f"(hp) : "memory");
        }
        __syncthreads();
        if (tid == 0 && t < T_STEPS - 1) {
            __threadfence();
            asm volatile("st.global.cg.u32 [%0], %1;"
                         :: "l"(&g_flags[bid]), "r"((unsigned)(t + 1)) : "memory");
        }

        hs[bsub * WR + j0 + col] = hp;

        y[((size_t)t * BATCH + b) * HID + j] = hp;
        if (t == T_STEPS - 1) hn_out[(size_t)b * HID + j] = hp;

        xr = nxr; xz = nxz; xn = nxn;
    }

    __syncthreads();
    if (tid == 0) {
        unsigned gen = g_end_gen[grp];
        __threadfence();
        if (atomicAdd(&g_end_cnt[grp], 1u) == 15u) {
            g_end_cnt[grp] = 0u;
            __threadfence();
            g_end_gen[grp] = gen + 1u;
        } else {
            while (g_end_gen[grp] == gen) { __nanosleep(32); }
        }
        g_flags[bid] = 0u;
        __threadfence();
    }
}

// ---------------- launch ----------------
extern "C" void kernel_launch(void* const* d_in, const int* in_sizes, int n_in,
                              void* d_out, int out_size) {
    const float* x    = (const float*)d_in[0];
    const float* Wih0 = (const float*)d_in[1];
    const float* Whh0 = (const float*)d_in[2];
    const float* bih0 = (const float*)d_in[3];
    const float* bhh0 = (const float*)d_in[4];
    const float* Wih1 = (const float*)d_in[5];
    const float* Whh1 = (const float*)d_in[6];
    const float* bih1 = (const float*)d_in[7];
    const float* bhh1 = (const float*)d_in[8];

    float* out = (float*)d_out;
    float* y1  = out;
    float* hn0 = out + (size_t)T_STEPS * BATCH * HID;
    float* hn1 = hn0 + BATCH * HID;

    float *xg, *y0;
    cudaGetSymbolAddress((void**)&xg, g_xg);
    cudaGetSymbolAddress((void**)&y0, g_y0);

    const int clu_smem = (4 + 96 * WR + 16 * WR) * 4;   // 231,184 B
    const int fb_smem  = (96 * WR + 8 * WR) * 4;        // 214,656 B

    cudaFuncSetAttribute(gru_rec_cluster, cudaFuncAttributeMaxDynamicSharedMemorySize, clu_smem);
    cudaFuncSetAttribute(gru_rec_cluster, cudaFuncAttributeNonPortableClusterSizeAllowed, 1);
    cudaFuncSetAttribute(gru_rec_fallback, cudaFuncAttributeMaxDynamicSharedMemorySize, fb_smem);

    // decide (stream-free, deterministic): can we run 16-CTA clusters?
    cudaLaunchConfig_t cfg = {};
    cfg.gridDim  = dim3(NB_REC, 1, 1);
    cfg.blockDim = dim3(NT_REC, 1, 1);
    cfg.dynamicSmemBytes = clu_smem;
    cfg.stream = 0;
    cudaLaunchAttribute attrs[1];
    attrs[0].id = cudaLaunchAttributeClusterDimension;
    attrs[0].val.clusterDim = {CLU, 1, 1};
    cfg.attrs = attrs;
    cfg.numAttrs = 1;

    int maxc = 0;
    cudaError_t qe = cudaOccupancyMaxPotentialClusterSize(&maxc, (void*)gru_rec_cluster, &cfg);
    const bool use_cluster = (qe == cudaSuccess && maxc >= CLU);
    if (qe != cudaSuccess) (void)cudaGetLastError();   // clear sticky error

    dim3 ggrid(12, 256);

    gemm_bias_kernel<<<ggrid, 256>>>(x, Wih0, bih0, xg, 256);
    if (use_cluster) {
        cudaLaunchKernelEx(&cfg, gru_rec_cluster, xg, Whh0, bhh0, y0, hn0);
    } else {
        gru_rec_fallback<<<NB_REC, NT_REC, fb_smem>>>(xg, Whh0, bhh0, y0, hn0);
    }
    gemm_bias_kernel<<<ggrid, 256>>>(y0, Wih1, bih1, xg, 512);
    if (use_cluster) {
        cudaLaunchKernelEx(&cfg, gru_rec_cluster, xg, Whh1, bhh1, y1, hn1);
    } else {
        gru_rec_fallback<<<NB_REC, NT_REC, fb_smem>>>(xg, Whh1, bhh1, y1, hn1);
    }
}

// round 11
// speedup vs baseline: 1.1020x; 1.1020x over previous
#include <cuda_runtime.h>

#define T_STEPS 512
#define BATCH   64
#define HID     512
#define GATES3  1536
#define NB_REC  64
#define NT_REC  512
#define WR      516   // float stride for smem rows (conflict-free: 516 % 32 == 4)

// ---------------- scratch (static device allocations; no cudaMalloc) ----------------
__device__ float g_xg[(size_t)T_STEPS * BATCH * GATES3]; // precomputed input gates
__device__ float g_y0[(size_t)T_STEPS * BATCH * HID];    // layer-0 output
__device__ float g_hx[2 * BATCH * HID];                  // ping-pong h exchange [parity][b][j]
__device__ unsigned g_flags[NB_REC];                     // per-block step flags
__device__ unsigned g_end_cnt[4];
__device__ volatile unsigned g_end_gen[4];

// ---------------- packed fp32x2 FMA (Blackwell FFMA2) ----------------
__device__ __forceinline__ float2 ffma2(float2 a, float2 b, float2 c) {
    float2 d;
    asm("fma.rn.f32x2 %0, %1, %2, %3;"
        : "=l"(reinterpret_cast<unsigned long long&>(d))
        : "l"(reinterpret_cast<unsigned long long&>(a)),
          "l"(reinterpret_cast<unsigned long long&>(b)),
          "l"(reinterpret_cast<unsigned long long&>(c)));
    return d;
}

__device__ __forceinline__ float fast_sigmoid(float x) {
    return __fdividef(1.f, 1.f + __expf(-x));
}
__device__ __forceinline__ float fast_tanh(float x) {
    float r;
    asm("tanh.approx.f32 %0, %1;" : "=f"(r) : "f"(x));
    return r;
}

// ---------------- GEMM: out[M,N] = A[M,K] * W[N,K]^T + bias (R2 version, known-good) ----
__global__ void __launch_bounds__(256) gemm_bias_kernel(
    const float* __restrict__ A, const float* __restrict__ W,
    const float* __restrict__ bias, float* __restrict__ out, int K)
{
    __shared__ float As[16 * 132];
    __shared__ float Bs[16 * 132];

    const int tid = threadIdx.x;
    const int m0 = blockIdx.y * 128;
    const int n0 = blockIdx.x * 128;
    const int tm = tid >> 4;
    const int tn = tid & 15;

    float2 c2[8][4];
#pragma unroll
    for (int i = 0; i < 8; ++i)
#pragma unroll
        for (int p = 0; p < 4; ++p) c2[i][p] = make_float2(0.f, 0.f);

    for (int kt = 0; kt < K; kt += 16) {
#pragma unroll
        for (int u = 0; u < 2; ++u) {
            int s   = tid + u * 256;
            int row = s >> 2;
            int c4  = s & 3;
            float4 av = *(const float4*)(A + (size_t)(m0 + row) * K + kt + c4 * 4);
            As[(c4 * 4 + 0) * 132 + row] = av.x;
            As[(c4 * 4 + 1) * 132 + row] = av.y;
            As[(c4 * 4 + 2) * 132 + row] = av.z;
            As[(c4 * 4 + 3) * 132 + row] = av.w;
            float4 bv = *(const float4*)(W + (size_t)(n0 + row) * K + kt + c4 * 4);
            Bs[(c4 * 4 + 0) * 132 + row] = bv.x;
            Bs[(c4 * 4 + 1) * 132 + row] = bv.y;
            Bs[(c4 * 4 + 2) * 132 + row] = bv.z;
            Bs[(c4 * 4 + 3) * 132 + row] = bv.w;
        }
        __syncthreads();

#pragma unroll
        for (int kb = 0; kb < 16; ++kb) {
            float4 a0 = *(const float4*)(As + kb * 132 + tm * 8);
            float4 a1 = *(const float4*)(As + kb * 132 + tm * 8 + 4);
            float4 b0 = *(const float4*)(Bs + kb * 132 + tn * 8);
            float4 b1 = *(const float4*)(Bs + kb * 132 + tn * 8 + 4);
            float av[8] = {a0.x, a0.y, a0.z, a0.w, a1.x, a1.y, a1.z, a1.w};
            float2 bp[4] = {make_float2(b0.x, b0.y), make_float2(b0.z, b0.w),
                            make_float2(b1.x, b1.y), make_float2(b1.z, b1.w)};
#pragma unroll
            for (int i = 0; i < 8; ++i) {
                float2 as = make_float2(av[i], av[i]);
#pragma unroll
                for (int p = 0; p < 4; ++p) c2[i][p] = ffma2(as, bp[p], c2[i][p]);
            }
        }
        __syncthreads();
    }

    const float4 bb0 = *(const float4*)(bias + n0 + tn * 8);
    const float4 bb1 = *(const float4*)(bias + n0 + tn * 8 + 4);
#pragma unroll
    for (int i = 0; i < 8; ++i) {
        int m = m0 + tm * 8 + i;
        float4 o0 = make_float4(c2[i][0].x + bb0.x, c2[i][0].y + bb0.y,
                                c2[i][1].x + bb0.z, c2[i][1].y + bb0.w);
        float4 o1 = make_float4(c2[i][2].x + bb1.x, c2[i][2].y + bb1.y,
                                c2[i][3].x + bb1.z, c2[i][3].y + bb1.w);
        float* dst = out + (size_t)m * GATES3 + n0 + tn * 8;
        *(float4*)(dst)     = o0;
        *(float4*)(dst + 4) = o1;
    }
}

// ---------------- persistent GRU recurrence ----------------
// 64 blocks = 16 col-groups x 4 batch-groups (16 batches each).
// 512 threads = 32 cols x 16 batches: thread = 1 col, 3 gates, 1 batch, full k=512.
// NO reductions, NO gate exchange — R5/R9 champion body, 4 warps/SMSP for latency hiding.
__global__ void __launch_bounds__(NT_REC, 1) gru_rec_kernel(
    const float* __restrict__ xg, const float* __restrict__ Whh,
    const float* __restrict__ bhh, float* __restrict__ y,
    float* __restrict__ hn_out)
{
    extern __shared__ float smem[];
    float* Ws = smem;                 // 96 rows (g*32+col) x 516 floats
    float* hs = smem + 96 * WR;       // 16 rows (batch) x 516 floats

    const int tid  = threadIdx.x;
    const int bid  = blockIdx.x;
    const int cg   = bid & 15;
    const int grp  = bid >> 4;        // 0..3
    const int j0   = cg * 32;
    const int b0   = grp * 16;
    const int col  = tid >> 4;        // 0..31
    const int bsub = tid & 15;        // 0..15
    const int b    = b0 + bsub;
    const int j    = j0 + col;

    // one-time: W_hh slice (96 rows x 512, coalesced gmem read)
    for (int idx = tid; idx < 96 * 512; idx += NT_REC) {
        int row = idx >> 9;
        int k   = idx & 511;
        int g   = row >> 5;
        int c   = row & 31;
        Ws[row * WR + k] = Whh[(size_t)(g * HID + j0 + c) * HID + k];
    }
    for (int idx = tid; idx < 16 * WR; idx += NT_REC) hs[idx] = 0.f;

    const float bhr = bhh[j];
    const float bhz = bhh[HID + j];
    const float bhn = bhh[2 * HID + j];

    const float* wr = Ws + col * WR;
    const float* wz = Ws + (32 + col) * WR;
    const float* wn = Ws + (64 + col) * WR;
    const float* hb = hs + bsub * WR;

    const size_t xofs = (size_t)b * GATES3 + j;
    float xr = xg[xofs];
    float xz = xg[xofs + HID];
    float xn = xg[xofs + 2 * HID];

    // staging geometry: 2048 float4 total (16 batches x 128 quarters), 4 per thread;
    // own col-block (kq>>3 == cg) skipped — written directly at finalize.
    float hp = 0.f;   // own h, in regs
    __syncthreads();

    for (int t = 0; t < T_STEPS; ++t) {
        if (t > 0) {
            // group barrier: 15 remote flags (own block's slice already in smem)
            if (tid < 16 && tid != cg) {
                const unsigned* fp = &g_flags[grp * 16 + tid];
                unsigned v;
                do {
                    asm volatile("ld.acquire.gpu.global.u32 %0, [%1];" : "=r"(v) : "l"(fp));
                } while (v < (unsigned)t);
            }
            __syncthreads();
            // stage remote h (15/16 of 32 KB) for this group's 16 batches
            const float* hsrc = g_hx + (size_t)(t & 1) * BATCH * HID;
#pragma unroll
            for (int i = 0; i < 4; ++i) {
                int idx = tid + i * NT_REC;
                int bb  = idx >> 7;            // 0..15
                int kq  = idx & 127;           // float4 quarter
                if ((kq >> 3) != cg) {
                    float4 hv = __ldcg((const float4*)(hsrc + (size_t)(b0 + bb) * HID + kq * 4));
                    *(float4*)(hs + bb * WR + kq * 4) = hv;
                }
            }
            __syncthreads();
        }

        // prefetch next step's xg early: LDG latency hides under the FMA loop
        float nxr = 0.f, nxz = 0.f, nxn = 0.f;
        if (t + 1 < T_STEPS) {
            const float* xp = xg + (size_t)(t + 1) * BATCH * GATES3 + xofs;
            nxr = __ldg(xp);
            nxz = __ldg(xp + HID);
            nxn = __ldg(xp + 2 * HID);
        }

        // full-k dot, FFMA2 packed along k: 3 gates x 1 col x 1 batch
        float2 r0 = {0, 0}, r1 = {0, 0};
        float2 z0 = {0, 0}, z1 = {0, 0};
        float2 n0 = {0, 0}, n1 = {0, 0};
#pragma unroll 8
        for (int k = 0; k < HID; k += 8) {
            float4 h0 = *(const float4*)(hb + k);
            float4 h1 = *(const float4*)(hb + k + 4);
            float4 a0 = *(const float4*)(wr + k);
            float4 a1 = *(const float4*)(wr + k + 4);
            float4 c0 = *(const float4*)(wz + k);
            float4 c1 = *(const float4*)(wz + k + 4);
            float4 d0 = *(const float4*)(wn + k);
            float4 d1 = *(const float4*)(wn + k + 4);
            r0 = ffma2(make_float2(a0.x, a0.y), make_float2(h0.x, h0.y), r0);
            r1 = ffma2(make_float2(a0.z, a0.w), make_float2(h0.z, h0.w), r1);
            z0 = ffma2(make_float2(c0.x, c0.y), make_float2(h0.x, h0.y), z0);
            z1 = ffma2(make_float2(c0.z, c0.w), make_float2(h0.z, h0.w), z1);
            n0 = ffma2(make_float2(d0.x, d0.y), make_float2(h0.x, h0.y), n0);
            n1 = ffma2(make_float2(d0.z, d0.w), make_float2(h0.z, h0.w), n1);
            r0 = ffma2(make_float2(a1.x, a1.y), make_float2(h1.x, h1.y), r0);
            r1 = ffma2(make_float2(a1.z, a1.w), make_float2(h1.z, h1.w), r1);
            z0 = ffma2(make_float2(c1.x, c1.y), make_float2(h1.x, h1.y), z0);
            z1 = ffma2(make_float2(c1.z, c1.w), make_float2(h1.z, h1.w), z1);
            n0 = ffma2(make_float2(d1.x, d1.y), make_float2(h1.x, h1.y), n0);
            n1 = ffma2(make_float2(d1.z, d1.w), make_float2(h1.z, h1.w), n1);
        }
        float hr = r0.x + r0.y + r1.x + r1.y + bhr;
        float hz = z0.x + z0.y + z1.x + z1.y + bhz;
        float hn = n0.x + n0.y + n1.x + n1.y + bhn;

        // finalize (fast approx transcendentals; rel_err ~4e-6, OK vs 1e-3)
        float rg = fast_sigmoid(xr + hr);
        float zg = fast_sigmoid(xz + hz);
        float ng = fast_tanh(xn + rg * hn);
        hp = (1.f - zg) * ng + zg * hp;

        // publish h to L2 FIRST (critical path for remote blocks), then flag
        {
            float* hdst = g_hx + (size_t)((t + 1) & 1) * BATCH * HID + (size_t)b * HID + j;
            asm volatile("st.global.cg.f32 [%0], %1;" :: "l"(hdst), "f"(hp) : "memory");
        }
        __syncthreads();
        if (tid == 0 && t < T_STEPS - 1) {
            __threadfence();
            asm volatile("st.global.cg.u32 [%0], %1;"
                         :: "l"(&g_flags[bid]), "r"((unsigned)(t + 1)) : "memory");
        }

        // own-slice shortcut: write own h directly into smem for next step
        hs[bsub * WR + j0 + col] = hp;

        // off critical path: y store, hn store
        y[((size_t)t * BATCH + b) * HID + j] = hp;
        if (t == T_STEPS - 1) hn_out[(size_t)b * HID + j] = hp;

        xr = nxr; xz = nxz; xn = nxn;
    }

    // end-of-launch: group gen-barrier (replay-safe), reset own flag
    __syncthreads();
    if (tid == 0) {
        unsigned gen = g_end_gen[grp];
        __threadfence();
        if (atomicAdd(&g_end_cnt[grp], 1u) == 15u) {
            g_end_cnt[grp] = 0u;
            __threadfence();
            g_end_gen[grp] = gen + 1u;
        } else {
            while (g_end_gen[grp] == gen) { __nanosleep(32); }
        }
        g_flags[bid] = 0u;
        __threadfence();
    }
}

// ---------------- launch ----------------
extern "C" void kernel_launch(void* const* d_in, const int* in_sizes, int n_in,
                              void* d_out, int out_size) {
    const float* x    = (const float*)d_in[0];
    const float* Wih0 = (const float*)d_in[1];
    const float* Whh0 = (const float*)d_in[2];
    const float* bih0 = (const float*)d_in[3];
    const float* bhh0 = (const float*)d_in[4];
    const float* Wih1 = (const float*)d_in[5];
    const float* Whh1 = (const float*)d_in[6];
    const float* bih1 = (const float*)d_in[7];
    const float* bhh1 = (const float*)d_in[8];

    float* out = (float*)d_out;
    float* y1  = out;
    float* hn0 = out + (size_t)T_STEPS * BATCH * HID;
    float* hn1 = hn0 + BATCH * HID;

    float *xg, *y0;
    cudaGetSymbolAddress((void**)&xg, g_xg);
    cudaGetSymbolAddress((void**)&y0, g_y0);

    const int rec_smem = (96 * WR + 16 * WR) * 4;  // 231,168 B
    cudaFuncSetAttribute(gru_rec_kernel, cudaFuncAttributeMaxDynamicSharedMemorySize, rec_smem);

    dim3 ggrid(12, 256);

    gemm_bias_kernel<<<ggrid, 256>>>(x, Wih0, bih0, xg, 256);
    gru_rec_kernel<<<NB_REC, NT_REC, rec_smem>>>(xg, Whh0, bhh0, y0, hn0);
    gemm_bias_kernel<<<ggrid, 256>>>(y0, Wih1, bih1, xg, 512);
    gru_rec_kernel<<<NB_REC, NT_REC, rec_smem>>>(xg, Whh1, bhh1, y1, hn1);
}

// round 13
// speedup vs baseline: 2.6706x; 2.4233x over previous
#include <cuda_runtime.h>

#define T_STEPS 512
#define BATCH   64
#define HID     512
#define GATES3  1536
#define NB_REC  128
#define NT_REC  128
#define WROWF   1040   // W row stride in floats (2*520; k-half offset 520, 16B-aligned)
#define KHOFF   520    // k-half offset within a W row
#define HR      516    // h row stride in floats (k-half offset 260)

// ---------------- scratch (static device allocations; no cudaMalloc) ----------------
__device__ float g_xg[(size_t)T_STEPS * BATCH * GATES3]; // precomputed input gates
__device__ float g_y0[(size_t)T_STEPS * BATCH * HID];    // layer-0 output
__device__ float g_hx[2 * BATCH * HID];                  // ping-pong h exchange [parity][b][j]
__device__ unsigned g_flags[NB_REC];                     // per-block step flags
__device__ unsigned g_end_cnt[8];
__device__ volatile unsigned g_end_gen[8];

// ---------------- packed fp32x2 FMA (Blackwell FFMA2) ----------------
__device__ __forceinline__ float2 ffma2(float2 a, float2 b, float2 c) {
    float2 d;
    asm("fma.rn.f32x2 %0, %1, %2, %3;"
        : "=l"(reinterpret_cast<unsigned long long&>(d))
        : "l"(reinterpret_cast<unsigned long long&>(a)),
          "l"(reinterpret_cast<unsigned long long&>(b)),
          "l"(reinterpret_cast<unsigned long long&>(c)));
    return d;
}

__device__ __forceinline__ float fast_sigmoid(float x) {
    return __fdividef(1.f, 1.f + __expf(-x));
}
__device__ __forceinline__ float fast_tanh(float x) {
    float r;
    asm("tanh.approx.f32 %0, %1;" : "=f"(r) : "f"(x));
    return r;
}

// ---------------- GEMM: out[M,N] = A[M,K] * W[N,K]^T + bias (R2 version, known-good) ----
__global__ void __launch_bounds__(256) gemm_bias_kernel(
    const float* __restrict__ A, const float* __restrict__ W,
    const float* __restrict__ bias, float* __restrict__ out, int K)
{
    __shared__ float As[16 * 132];
    __shared__ float Bs[16 * 132];

    const int tid = threadIdx.x;
    const int m0 = blockIdx.y * 128;
    const int n0 = blockIdx.x * 128;
    const int tm = tid >> 4;
    const int tn = tid & 15;

    float2 c2[8][4];
#pragma unroll
    for (int i = 0; i < 8; ++i)
#pragma unroll
        for (int p = 0; p < 4; ++p) c2[i][p] = make_float2(0.f, 0.f);

    for (int kt = 0; kt < K; kt += 16) {
#pragma unroll
        for (int u = 0; u < 2; ++u) {
            int s   = tid + u * 256;
            int row = s >> 2;
            int c4  = s & 3;
            float4 av = *(const float4*)(A + (size_t)(m0 + row) * K + kt + c4 * 4);
            As[(c4 * 4 + 0) * 132 + row] = av.x;
            As[(c4 * 4 + 1) * 132 + row] = av.y;
            As[(c4 * 4 + 2) * 132 + row] = av.z;
            As[(c4 * 4 + 3) * 132 + row] = av.w;
            float4 bv = *(const float4*)(W + (size_t)(n0 + row) * K + kt + c4 * 4);
            Bs[(c4 * 4 + 0) * 132 + row] = bv.x;
            Bs[(c4 * 4 + 1) * 132 + row] = bv.y;
            Bs[(c4 * 4 + 2) * 132 + row] = bv.z;
            Bs[(c4 * 4 + 3) * 132 + row] = bv.w;
        }
        __syncthreads();

#pragma unroll
        for (int kb = 0; kb < 16; ++kb) {
            float4 a0 = *(const float4*)(As + kb * 132 + tm * 8);
            float4 a1 = *(const float4*)(As + kb * 132 + tm * 8 + 4);
            float4 b0 = *(const float4*)(Bs + kb * 132 + tn * 8);
            float4 b1 = *(const float4*)(Bs + kb * 132 + tn * 8 + 4);
            float av[8] = {a0.x, a0.y, a0.z, a0.w, a1.x, a1.y, a1.z, a1.w};
            float2 bp[4] = {make_float2(b0.x, b0.y), make_float2(b0.z, b0.w),
                            make_float2(b1.x, b1.y), make_float2(b1.z, b1.w)};
#pragma unroll
            for (int i = 0; i < 8; ++i) {
                float2 as = make_float2(av[i], av[i]);
#pragma unroll
                for (int p = 0; p < 4; ++p) c2[i][p] = ffma2(as, bp[p], c2[i][p]);
            }
        }
        __syncthreads();
    }

    const float4 bb0 = *(const float4*)(bias + n0 + tn * 8);
    const float4 bb1 = *(const float4*)(bias + n0 + tn * 8 + 4);
#pragma unroll
    for (int i = 0; i < 8; ++i) {
        int m = m0 + tm * 8 + i;
        float4 o0 = make_float4(c2[i][0].x + bb0.x, c2[i][0].y + bb0.y,
                                c2[i][1].x + bb0.z, c2[i][1].y + bb0.w);
        float4 o1 = make_float4(c2[i][2].x + bb1.x, c2[i][2].y + bb1.y,
                                c2[i][3].x + bb1.z, c2[i][3].y + bb1.w);
        float* dst = out + (size_t)m * GATES3 + n0 + tn * 8;
        *(float4*)(dst)     = o0;
        *(float4*)(dst + 4) = o1;
    }
}

// ---------------- persistent GRU recurrence ----------------
// 128 blocks = 16 col-groups x 8 batch-groups. 128 threads:
// tid = cp*8 + bq*2 + kk  (cp: 16 col-pairs, bq: 4 batch-pairs, kk: k-half).
// Thread tile: 2 cols x 3 gates x 2 batches x K=256. k-reduction = __shfl_xor(1).
// LDS.128/block/step = 2048 (half of R5 champion).
__global__ void __launch_bounds__(NT_REC, 1) gru_rec_kernel(
    const float* __restrict__ xg, const float* __restrict__ Whh,
    const float* __restrict__ bhh, float* __restrict__ y,
    float* __restrict__ hn_out)
{
    extern __shared__ float smem[];
    float* Ws = smem;                  // 48 rows (g*16+cp) x 1040 floats (col-pair interleaved)
    float* hs = smem + 48 * WROWF;     // 8 rows (batch) x 516 floats (k-half at +260)

    const int tid = threadIdx.x;
    const int bid = blockIdx.x;
    const int cg  = bid & 15;
    const int grp = bid >> 4;
    const int j0  = cg * 32;
    const int b0  = grp * 8;
    const int cp  = tid >> 3;          // 0..15
    const int bq  = (tid >> 1) & 3;    // 0..3
    const int kk  = tid & 1;           // 0..1
    const int jj  = j0 + cp * 2;       // first of this thread's col pair
    const int bA  = b0 + bq * 2;       // first of this thread's batch pair
    const int bB  = bA + 1;

    // one-time: W_hh slice, col-pair interleaved + k-half split:
    // Ws[(g*16+cp)*1040 + kh*520 + kl*2 + c] = Whh[g*512 + j0+2cp+c][kh*256+kl]
    for (int idx = tid; idx < 96 * 512; idx += NT_REC) {
        int row = idx >> 9;            // g*32 + cc
        int k   = idx & 511;
        int g   = row >> 5;
        int cc  = row & 31;
        int cpp = cc >> 1;
        int c   = cc & 1;
        int kh  = k >> 8;
        int kl  = k & 255;
        Ws[(g * 16 + cpp) * WROWF + kh * KHOFF + kl * 2 + c] =
            Whh[(size_t)(g * HID + j0 + cc) * HID + k];
    }
    for (int idx = tid; idx < 8 * HR; idx += NT_REC) hs[idx] = 0.f;

    // biases for this thread's col pair (only kk==0 finalizes)
    const float2 bhr = *(const float2*)(bhh + jj);
    const float2 bhz = *(const float2*)(bhh + HID + jj);
    const float2 bhn = *(const float2*)(bhh + 2 * HID + jj);

    const float* wr = Ws + cp * WROWF + kk * KHOFF;
    const float* wz = wr + 16 * WROWF;
    const float* wn = wr + 32 * WROWF;
    const float* h0p = hs + (bq * 2) * HR + kk * 260;
    const float* h1p = h0p + HR;

    // xg offsets (kk==0 threads only; 2 batches x 3 gates x col-pair)
    const size_t xoA = (size_t)bA * GATES3 + jj;
    const size_t xoB = (size_t)bB * GATES3 + jj;
    float2 xrA = {0,0}, xzA = {0,0}, xnA = {0,0};
    float2 xrB = {0,0}, xzB = {0,0}, xnB = {0,0};
    if (kk == 0) {
        xrA = *(const float2*)(xg + xoA);
        xzA = *(const float2*)(xg + xoA + HID);
        xnA = *(const float2*)(xg + xoA + 2 * HID);
        xrB = *(const float2*)(xg + xoB);
        xzB = *(const float2*)(xg + xoB + HID);
        xnB = *(const float2*)(xg + xoB + 2 * HID);
    }

    // own h (col pair x 2 batches), kept in kk==0 regs
    float2 hpA = {0,0}, hpB = {0,0};

    // own-slice smem offset for col j: +4 if j >= 256 (k-half layout)
    const int own_off = jj + ((cg >= 8) ? 4 : 0);
    __syncthreads();

    for (int t = 0; t < T_STEPS; ++t) {
        if (t > 0) {
            if (tid < 16 && tid != cg) {
                const unsigned* fp = &g_flags[grp * 16 + tid];
                unsigned v;
                do {
                    asm volatile("ld.acquire.gpu.global.u32 %0, [%1];" : "=r"(v) : "l"(fp));
                } while (v < (unsigned)t);
            }
            __syncthreads();
            // stage remote h: 1024 float4 over 128 threads, skip own col-block
            const float* hsrc = g_hx + (size_t)(t & 1) * BATCH * HID;
#pragma unroll
            for (int i = 0; i < 8; ++i) {
                int idx = tid + i * NT_REC;
                int bb  = idx >> 7;            // 0..7
                int kq  = idx & 127;           // float4 quarter
                if ((kq >> 3) != cg) {
                    float4 hv = __ldcg((const float4*)(hsrc + (size_t)(b0 + bb) * HID + kq * 4));
                    *(float4*)(hs + bb * HR + ((kq >= 64) ? 4 : 0) + kq * 4) = hv;
                }
            }
            __syncthreads();
        }

        // prefetch next step's xg (kk==0 only; hides under the dot)
        float2 nxrA = {0,0}, nxzA = {0,0}, nxnA = {0,0};
        float2 nxrB = {0,0}, nxzB = {0,0}, nxnB = {0,0};
        if (kk == 0 && t + 1 < T_STEPS) {
            const float* xpA = xg + (size_t)(t + 1) * BATCH * GATES3 + xoA;
            const float* xpB = xg + (size_t)(t + 1) * BATCH * GATES3 + xoB;
            nxrA = *(const float2*)(xpA);
            nxzA = *(const float2*)(xpA + HID);
            nxnA = *(const float2*)(xpA + 2 * HID);
            nxrB = *(const float2*)(xpB);
            nxzB = *(const float2*)(xpB + HID);
            nxnB = *(const float2*)(xpB + 2 * HID);
        }

        // half-k dot: 3 gates x 2 cols (FFMA2-packed) x 2 batches
        float2 arA = {0,0}, azA = {0,0}, anA = {0,0};
        float2 arB = {0,0}, azB = {0,0}, anB = {0,0};
#pragma unroll 4
        for (int k = 0; k < 256; k += 4) {
            float4 hA = *(const float4*)(h0p + k);     // batch A: h[k..k+3]
            float4 hB = *(const float4*)(h1p + k);     // batch B
            float4 r01 = *(const float4*)(wr + k * 2);       // (r[c0,k],r[c1,k],r[c0,k+1],r[c1,k+1])
            float4 r23 = *(const float4*)(wr + k * 2 + 4);
            float4 z01 = *(const float4*)(wz + k * 2);
            float4 z23 = *(const float4*)(wz + k * 2 + 4);
            float4 n01 = *(const float4*)(wn + k * 2);
            float4 n23 = *(const float4*)(wn + k * 2 + 4);
            float2 w0, w1, w2, w3;
            // r gate
            w0 = make_float2(r01.x, r01.y); w1 = make_float2(r01.z, r01.w);
            w2 = make_float2(r23.x, r23.y); w3 = make_float2(r23.z, r23.w);
            arA = ffma2(w0, make_float2(hA.x, hA.x), arA);
            arA = ffma2(w1, make_float2(hA.y, hA.y), arA);
            arA = ffma2(w2, make_float2(hA.z, hA.z), arA);
            arA = ffma2(w3, make_float2(hA.w, hA.w), arA);
            arB = ffma2(w0, make_float2(hB.x, hB.x), arB);
            arB = ffma2(w1, make_float2(hB.y, hB.y), arB);
            arB = ffma2(w2, make_float2(hB.z, hB.z), arB);
            arB = ffma2(w3, make_float2(hB.w, hB.w), arB);
            // z gate
            w0 = make_float2(z01.x, z01.y); w1 = make_float2(z01.z, z01.w);
            w2 = make_float2(z23.x, z23.y); w3 = make_float2(z23.z, z23.w);
            azA = ffma2(w0, make_float2(hA.x, hA.x), azA);
            azA = ffma2(w1, make_float2(hA.y, hA.y), azA);
            azA = ffma2(w2, make_float2(hA.z, hA.z), azA);
            azA = ffma2(w3, make_float2(hA.w, hA.w), azA);
            azB = ffma2(w0, make_float2(hB.x, hB.x), azB);
            azB = ffma2(w1, make_float2(hB.y, hB.y), azB);
            azB = ffma2(w2, make_float2(hB.z, hB.z), azB);
            azB = ffma2(w3, make_float2(hB.w, hB.w), azB);
            // n gate
            w0 = make_float2(n01.x, n01.y); w1 = make_float2(n01.z, n01.w);
            w2 = make_float2(n23.x, n23.y); w3 = make_float2(n23.z, n23.w);
            anA = ffma2(w0, make_float2(hA.x, hA.x), anA);
            anA = ffma2(w1, make_float2(hA.y, hA.y), anA);
            anA = ffma2(w2, make_float2(hA.z, hA.z), anA);
            anA = ffma2(w3, make_float2(hA.w, hA.w), anA);
            anB = ffma2(w0, make_float2(hB.x, hB.x), anB);
            anB = ffma2(w1, make_float2(hB.y, hB.y), anB);
            anB = ffma2(w2, make_float2(hB.z, hB.z), anB);
            anB = ffma2(w3, make_float2(hB.w, hB.w), anB);
        }

        // cross-k-half reduction: partner = lane^1 (same warp)
        arA.x += __shfl_xor_sync(0xffffffffu, arA.x, 1);
        arA.y += __shfl_xor_sync(0xffffffffu, arA.y, 1);
        azA.x += __shfl_xor_sync(0xffffffffu, azA.x, 1);
        azA.y += __shfl_xor_sync(0xffffffffu, azA.y, 1);
        anA.x += __shfl_xor_sync(0xffffffffu, anA.x, 1);
        anA.y += __shfl_xor_sync(0xffffffffu, anA.y, 1);
        arB.x += __shfl_xor_sync(0xffffffffu, arB.x, 1);
        arB.y += __shfl_xor_sync(0xffffffffu, arB.y, 1);
        azB.x += __shfl_xor_sync(0xffffffffu, azB.x, 1);
        azB.y += __shfl_xor_sync(0xffffffffu, azB.y, 1);
        anB.x += __shfl_xor_sync(0xffffffffu, anB.x, 1);
        anB.y += __shfl_xor_sync(0xffffffffu, anB.y, 1);

        if (kk == 0) {
            // finalize 4 h values (2 cols x 2 batches)
            float rAx = fast_sigmoid(xrA.x + arA.x + bhr.x);
            float rAy = fast_sigmoid(xrA.y + arA.y + bhr.y);
            float zAx = fast_sigmoid(xzA.x + azA.x + bhz.x);
            float zAy = fast_sigmoid(xzA.y + azA.y + bhz.y);
            float nAx = fast_tanh(xnA.x + rAx * (anA.x + bhn.x));
            float nAy = fast_tanh(xnA.y + rAy * (anA.y + bhn.y));
            hpA.x = (1.f - zAx) * nAx + zAx * hpA.x;
            hpA.y = (1.f - zAy) * nAy + zAy * hpA.y;

            float rBx = fast_sigmoid(xrB.x + arB.x + bhr.x);
            float rBy = fast_sigmoid(xrB.y + arB.y + bhr.y);
            float zBx = fast_sigmoid(xzB.x + azB.x + bhz.x);
            float zBy = fast_sigmoid(xzB.y + azB.y + bhz.y);
            float nBx = fast_tanh(xnB.x + rBx * (anB.x + bhn.x));
            float nBy = fast_tanh(xnB.y + rBy * (anB.y + bhn.y));
            hpB.x = (1.f - zBx) * nBx + zBx * hpB.x;
            hpB.y = (1.f - zBy) * nBy + zBy * hpB.y;

            // publish h to L2 FIRST (critical path for remote blocks)
            float* base = g_hx + (size_t)((t + 1) & 1) * BATCH * HID;
            asm volatile("st.global.cg.v2.f32 [%0], {%1, %2};"
                         :: "l"(base + (size_t)bA * HID + jj), "f"(hpA.x), "f"(hpA.y) : "memory");
            asm volatile("st.global.cg.v2.f32 [%0], {%1, %2};"
                         :: "l"(base + (size_t)bB * HID + jj), "f"(hpB.x), "f"(hpB.y) : "memory");
        }
        __syncthreads();
        if (tid == 0 && t < T_STEPS - 1) {
            __threadfence();
            asm volatile("st.global.cg.u32 [%0], %1;"
                         :: "l"(&g_flags[bid]), "r"((unsigned)(t + 1)) : "memory");
        }

        if (kk == 0) {
            // own-slice shortcut into smem (post-sync: safe vs this step's reads)
            *(float2*)(hs + (bq * 2) * HR + own_off)     = hpA;
            *(float2*)(hs + (bq * 2 + 1) * HR + own_off) = hpB;

            // off critical path: y store, hn store
            *(float2*)(y + ((size_t)t * BATCH + bA) * HID + jj) = hpA;
            *(float2*)(y + ((size_t)t * BATCH + bB) * HID + jj) = hpB;
            if (t == T_STEPS - 1) {
                *(float2*)(hn_out + (size_t)bA * HID + jj) = hpA;
                *(float2*)(hn_out + (size_t)bB * HID + jj) = hpB;
            }
            xrA = nxrA; xzA = nxzA; xnA = nxnA;
            xrB = nxrB; xzB = nxzB; xnB = nxnB;
        }
    }

    // end-of-launch: group gen-barrier (replay-safe), reset own flag
    __syncthreads();
    if (tid == 0) {
        unsigned gen = g_end_gen[grp];
        __threadfence();
        if (atomicAdd(&g_end_cnt[grp], 1u) == 15u) {
            g_end_cnt[grp] = 0u;
            __threadfence();
            g_end_gen[grp] = gen + 1u;
        } else {
            while (g_end_gen[grp] == gen) { __nanosleep(32); }
        }
        g_flags[bid] = 0u;
        __threadfence();
    }
}

// ---------------- launch ----------------
extern "C" void kernel_launch(void* const* d_in, const int* in_sizes, int n_in,
                              void* d_out, int out_size) {
    const float* x    = (const float*)d_in[0];
    const float* Wih0 = (const float*)d_in[1];
    const float* Whh0 = (const float*)d_in[2];
    const float* bih0 = (const float*)d_in[3];
    const float* bhh0 = (const float*)d_in[4];
    const float* Wih1 = (const float*)d_in[5];
    const float* Whh1 = (const float*)d_in[6];
    const float* bih1 = (const float*)d_in[7];
    const float* bhh1 = (const float*)d_in[8];

    float* out = (float*)d_out;
    float* y1  = out;
    float* hn0 = out + (size_t)T_STEPS * BATCH * HID;
    float* hn1 = hn0 + BATCH * HID;

    float *xg, *y0;
    cudaGetSymbolAddress((void**)&xg, g_xg);
    cudaGetSymbolAddress((void**)&y0, g_y0);

    const int rec_smem = (48 * WROWF + 8 * HR) * 4;  // 216,192 B
    cudaFuncSetAttribute(gru_rec_kernel, cudaFuncAttributeMaxDynamicSharedMemorySize, rec_smem);

    dim3 ggrid(12, 256);

    gemm_bias_kernel<<<ggrid, 256>>>(x, Wih0, bih0, xg, 256);
    gru_rec_kernel<<<NB_REC, NT_REC, rec_smem>>>(xg, Whh0, bhh0, y0, hn0);
    gemm_bias_kernel<<<ggrid, 256>>>(y0, Wih1, bih1, xg, 512);
    gru_rec_kernel<<<NB_REC, NT_REC, rec_smem>>>(xg, Whh1, bhh1, y1, hn1);
}